// round 1
// baseline (speedup 1.0000x reference)
#include <cuda_runtime.h>
#include <stdint.h>

#define BB   4
#define NN   1024
#define CC   80
#define KPC  100
#define MAXT 300
#define NEGV (-1e30f)
#define STHR 0.001f

// ---------------- scratch (no allocations allowed) ----------------
__device__ uint32_t g_mask[BB * NN * 32];       // per-image IoU>0.5 bit matrix
__device__ float    g_stage_s[BB * CC * KPC];   // per-class top-100 scores (NEGV = empty)
__device__ int      g_stage_b[BB * CC * KPC];   // per-class top-100 original box indices

// order-reversing float->uint map: s1 > s2  <=>  dbits(s1) < dbits(s2)
__device__ __forceinline__ uint32_t dbits(float f) {
    uint32_t u = __float_as_uint(f);
    return (u & 0x80000000u) ? u : (u ^ 0x7fffffffu);
}

// ---------------- K1: per-image pairwise IoU>0.5 bitmask ----------------
__global__ void __launch_bounds__(256) k_mask(const float* __restrict__ boxes) {
    __shared__ float sy1[NN], sx1[NN], sy2[NN], sx2[NN], sar[NN];
    const int b   = blockIdx.y;
    const int tid = threadIdx.x;

    #pragma unroll
    for (int k = 0; k < 4; k++) {
        int i = tid + k * 256;
        float4 bx = reinterpret_cast<const float4*>(boxes)[b * NN + i];
        float y1 = fminf(bx.x, bx.z), y2 = fmaxf(bx.x, bx.z);
        float x1 = fminf(bx.y, bx.w), x2 = fmaxf(bx.y, bx.w);
        sy1[i] = y1; sx1[i] = x1; sy2[i] = y2; sx2[i] = x2;
        sar[i] = (y2 - y1) * (x2 - x1);
    }
    __syncthreads();

    const int r0 = blockIdx.x * 32;
    #pragma unroll
    for (int k = 0; k < 4; k++) {
        int lin = tid + k * 256;          // 0..1023: 32 rows x 32 words
        int i   = r0 + (lin >> 5);
        int w   = lin & 31;
        float y1a = sy1[i], x1a = sx1[i], y2a = sy2[i], x2a = sx2[i], aa = sar[i];
        uint32_t bits = 0;
        #pragma unroll
        for (int jj = 0; jj < 32; jj++) {
            int j = w * 32 + jj;
            float ih    = fmaxf(fminf(y2a, sy2[j]) - fmaxf(y1a, sy1[j]), 0.0f);
            float iw    = fmaxf(fminf(x2a, sx2[j]) - fmaxf(x1a, sx1[j]), 0.0f);
            float inter = ih * iw;
            float uni   = fmaxf(aa + sar[j] - inter, 1e-12f);
            float iou   = __fdiv_rn(inter, uni);   // exact IEEE div, matches reference
            if (iou > 0.5f) bits |= (1u << jj);
        }
        g_mask[(b * NN + i) * 32 + w] = bits;
    }
}

// ---------------- K2: per-(image,class) sort + greedy NMS ----------------
__global__ void __launch_bounds__(512) k_nms(const float* __restrict__ scores) {
    __shared__ uint64_t keys[NN];     // (dbits(score)<<32) | orig_idx, ascending = score desc
    __shared__ float    sscore[NN];   // raw scores by orig idx
    __shared__ float    kept_s[KPC];
    __shared__ int      kept_i[KPC];
    __shared__ int      sh_kc;

    const int c   = blockIdx.x;
    const int b   = blockIdx.y;
    const int tid = threadIdx.x;

    #pragma unroll
    for (int k = 0; k < 2; k++) {
        int i  = tid + k * 512;
        float s = scores[(b * NN + i) * CC + c];
        sscore[i] = s;
        float sv  = (s > STHR) ? s : NEGV;
        keys[i]   = (((uint64_t)dbits(sv)) << 32) | (uint32_t)i;
    }
    __syncthreads();

    // bitonic sort ascending (=> score descending, stable by idx)
    for (int k = 2; k <= NN; k <<= 1) {
        for (int j = k >> 1; j > 0; j >>= 1) {
            #pragma unroll
            for (int t = 0; t < 2; t++) {
                int i2  = tid + t * 512;
                int ixj = i2 ^ j;
                if (ixj > i2) {
                    uint64_t a = keys[i2], d = keys[ixj];
                    bool up = ((i2 & k) == 0);
                    if ((a > d) == up) { keys[i2] = d; keys[ixj] = a; }
                }
            }
            __syncthreads();
        }
    }

    // greedy scan on warp 0, suppressed bitmap lane-distributed in registers
    if (tid < 32) {
        const uint32_t thrk = dbits(STHR);  // valid <=> hi < thrk
        uint32_t sup = 0;
        int kc = 0;

        const int D = 8;                    // mask-row prefetch depth (hides L2)
        uint64_t kbuf[D];
        uint32_t rowbuf[D];
        #pragma unroll
        for (int d = 0; d < D; d++) {
            uint64_t kk = keys[d];
            uint32_t o  = (uint32_t)kk & (NN - 1);
            kbuf[d]   = kk;
            rowbuf[d] = g_mask[(b * NN + o) * 32 + tid];
        }

        for (int p = 0; p < NN; p++) {
            int slot      = p & (D - 1);
            uint64_t kk   = kbuf[slot];
            uint32_t row  = rowbuf[slot];
            uint32_t o    = (uint32_t)kk & (NN - 1);
            if (p + D < NN) {                    // keep pipeline full
                uint64_t k2 = keys[p + D];
                kbuf[slot]   = k2;
                rowbuf[slot] = g_mask[(b * NN + ((uint32_t)k2 & (NN - 1))) * 32 + tid];
            }
            if ((uint32_t)(kk >> 32) >= thrk) break;   // invalid tail: stop

            uint32_t w = __shfl_sync(0xffffffffu, sup, (int)(o >> 5));
            if (!((w >> (o & 31)) & 1u)) {
                if (tid == 0) { kept_i[kc] = (int)o; kept_s[kc] = sscore[o]; }
                sup |= row;
                kc++;
                if (kc == KPC) break;   // later kept boxes cannot affect output
            }
        }
        if (tid == 0) sh_kc = kc;
    }
    __syncthreads();

    if (tid < KPC) {
        int kc   = sh_kc;
        int slot = (b * CC + c) * KPC + tid;
        if (tid < kc) { g_stage_s[slot] = kept_s[tid]; g_stage_b[slot] = kept_i[tid]; }
        else          { g_stage_s[slot] = NEGV;        g_stage_b[slot] = 0; }
    }
}

// ---------------- K3: per-image top-300 of 8000 + output assembly ----------------
__global__ void __launch_bounds__(1024) k_final(const float* __restrict__ boxes,
                                                float* __restrict__ out) {
    __shared__ uint64_t skeys[1024];
    __shared__ int      sred[32];
    __shared__ int      s_total;
    __shared__ int      s_cnt;

    const int b   = blockIdx.x;
    const int tid = threadIdx.x;
    const int M   = CC * KPC;   // 8000

    float vals[8];
    int   idxs[8];
    #pragma unroll
    for (int k = 0; k < 8; k++) {
        int f = tid + k * 1024;
        if (f < M) { vals[k] = g_stage_s[b * M + f]; idxs[k] = f; }
        else       { vals[k] = NEGV;                 idxs[k] = 0; }
    }

    // bisect pivot so that #(score > lo) in [300, ~300+eps]; falls back to lo=0
    float lo = 0.0f, hi = 1.0f;
    for (int it = 0; it < 30; it++) {
        float mid = 0.5f * (lo + hi);
        int cnt = 0;
        #pragma unroll
        for (int k = 0; k < 8; k++) cnt += (vals[k] > mid);
        #pragma unroll
        for (int off = 16; off; off >>= 1) cnt += __shfl_down_sync(0xffffffffu, cnt, off);
        if ((tid & 31) == 0) sred[tid >> 5] = cnt;
        __syncthreads();
        if (tid == 0) {
            int tot = 0;
            #pragma unroll
            for (int w = 0; w < 32; w++) tot += sred[w];
            s_total = tot;
        }
        __syncthreads();
        if (s_total >= MAXT) lo = mid; else hi = mid;
        __syncthreads();
    }

    if (tid == 0) s_cnt = 0;
    __syncthreads();
    #pragma unroll
    for (int k = 0; k < 8; k++) {
        if (vals[k] > lo) {
            int pos = atomicAdd(&s_cnt, 1);
            if (pos < 1024)
                skeys[pos] = (((uint64_t)dbits(vals[k])) << 32) | (uint32_t)idxs[k];
        }
    }
    __syncthreads();
    const int m = min(s_cnt, 1024);
    if (tid >= m) skeys[tid] = 0xFFFFFFFFFFFFFFFFull;
    __syncthreads();

    // bitonic sort 1024 u64 ascending (score desc, flat idx asc)
    for (int k = 2; k <= 1024; k <<= 1) {
        for (int j = k >> 1; j > 0; j >>= 1) {
            int ixj = tid ^ j;
            if (ixj > tid) {
                uint64_t a = skeys[tid], d = skeys[ixj];
                bool up = ((tid & k) == 0);
                if ((a > d) == up) { skeys[tid] = d; skeys[ixj] = a; }
            }
            __syncthreads();
        }
    }

    if (tid < MAXT) {
        bool valid = (tid < m);
        float sc = 0.0f, cls = 0.0f;
        float bx0 = 0.0f, bx1 = 0.0f, bx2 = 0.0f, bx3 = 0.0f;
        if (valid) {
            uint64_t kk = skeys[tid];
            int f = (int)((uint32_t)kk);
            sc  = g_stage_s[b * M + f];
            cls = (float)(f / KPC);
            int bidx = g_stage_b[b * M + f];
            float4 bv = reinterpret_cast<const float4*>(boxes)[b * NN + bidx];
            bx0 = fminf(fmaxf(bv.x, 0.0f), 1.0f);
            bx1 = fminf(fmaxf(bv.y, 0.0f), 1.0f);
            bx2 = fminf(fmaxf(bv.z, 0.0f), 1.0f);
            bx3 = fminf(fmaxf(bv.w, 0.0f), 1.0f);
        }
        out[b * MAXT + tid] = sc;                               // scores [B,300]
        float* ob = out + BB * MAXT + (b * MAXT + tid) * 4;     // boxes  [B,300,4]
        ob[0] = bx0; ob[1] = bx1; ob[2] = bx2; ob[3] = bx3;
        out[BB * MAXT * 5 + b * MAXT + tid] = cls;              // classes [B,300]
    }
    if (tid == 0) out[BB * MAXT * 6 + b] = (float)min(m, MAXT); // counts [B]
}

// ---------------- launch ----------------
extern "C" void kernel_launch(void* const* d_in, const int* in_sizes, int n_in,
                              void* d_out, int out_size) {
    const float* scores = (const float*)d_in[0];   // [4,1024,80] f32
    const float* boxes  = (const float*)d_in[1];   // [4,1024,1,4] f32
    float* out = (float*)d_out;

    k_mask<<<dim3(32, BB), 256>>>(boxes);
    k_nms<<<dim3(CC, BB), 512>>>(scores);
    k_final<<<BB, 1024>>>(boxes, out);
}

// round 2
// speedup vs baseline: 2.7527x; 2.7527x over previous
#include <cuda_runtime.h>
#include <stdint.h>

#define BB   4
#define NN   1024
#define CC   80
#define KPC  100
#define MAXT 300
#define NEGV (-1e30f)
#define STHR 0.001f
#define MSEL 256

// ---------------- scratch ----------------
__device__ uint32_t g_mask[BB * NN * 32];
__device__ float    g_stage_s[BB * CC * KPC];
__device__ int      g_stage_b[BB * CC * KPC];

__device__ __forceinline__ uint32_t dbits(float f) {
    uint32_t u = __float_as_uint(f);
    return (u & 0x80000000u) ? u : (u ^ 0x7fffffffu);
}
__device__ __forceinline__ float undbits_pos(uint32_t d) {
    return __uint_as_float(d ^ 0x7fffffffu);   // valid for positive originals
}

// ---------------- K1: pairwise IoU>0.5 bitmask ----------------
// 512 blocks x 256 threads; each thread = one (row, word32) pair.
// Decision is exact vs rn(inter/uni)>0.5:
//   rn(q)>0.5  <=>  q > 0.5+2^-25  <=>  2*inter - uni > uni*2^-24
// (2*inter exact; near the boundary 2*inter-uni is Sterbenz-exact; uni*2^-24 exact.)
__global__ void __launch_bounds__(256) k_mask(const float4* __restrict__ boxes) {
    __shared__ float4 sb[NN];   // canonicalized (y1,x1,y2,x2)
    const int b   = blockIdx.y;
    const int tid = threadIdx.x;

    #pragma unroll
    for (int k = 0; k < 4; k++) {
        int i = tid + k * 256;
        float4 v = boxes[b * NN + i];
        sb[i] = make_float4(fminf(v.x, v.z), fminf(v.y, v.w),
                            fmaxf(v.x, v.z), fmaxf(v.y, v.w));
    }
    __syncthreads();

    const int w = tid & 31;                      // word index
    const int i = blockIdx.x * 8 + (tid >> 5);   // row
    float4 A = sb[i];
    float aa = (A.z - A.x) * (A.w - A.y);
    uint32_t bits = 0;

    #pragma unroll
    for (int t = 0; t < 32; t++) {
        int c = (t + w) & 31;                    // rotation: no bank conflicts
        float4 Bx = sb[w * 32 + c];
        float ab    = (Bx.z - Bx.x) * (Bx.w - Bx.y);
        float ih    = fmaxf(fminf(A.z, Bx.z) - fmaxf(A.x, Bx.x), 0.0f);
        float iw2   = fmaxf(fminf(A.w, Bx.w) - fmaxf(A.y, Bx.y), 0.0f);
        float inter = ih * iw2;
        float uni   = fmaxf(aa + ab - inter, 1e-12f);
        float diff  = (inter + inter) - uni;
        if (diff > uni * 0x1p-24f) bits |= (1u << c);
    }
    g_mask[(b * NN + i) * 32 + w] = bits;
}

// ---------------- K2: per-(image,class) select + sort + greedy ----------------
__global__ void __launch_bounds__(512) k_nms(const float* __restrict__ scores) {
    __shared__ uint32_t hist[1025];          // bins, then exclusive cumsum
    __shared__ uint64_t selk[MSEL];
    __shared__ uint32_t rows[MSEL * 32];     // candidate mask rows (union: fallback keys)
    __shared__ float    kept_s[KPC];
    __shared__ int      kept_i[KPC];
    __shared__ uint32_t wsum[16];
    __shared__ int      s_cnt, s_bsel, s_kc;

    const int c   = blockIdx.x;
    const int b   = blockIdx.y;
    const int tid = threadIdx.x;
    const uint32_t BASE = 0x80F;             // dbits(1.0f) >> 19

    hist[2 * tid] = 0; hist[2 * tid + 1] = 0;
    if (tid == 0) { hist[1024] = 0; s_cnt = 0; s_bsel = 0; s_kc = 0; }

    uint32_t key[2], binv[2]; bool val[2];
    #pragma unroll
    for (int k = 0; k < 2; k++) {
        int i = tid + k * 512;
        float s = scores[(b * NN + i) * CC + c];
        val[k] = (s > STHR);
        key[k] = dbits(s);
        int raw = (int)(key[k] >> 19) - (int)BASE;
        binv[k] = (uint32_t)min(max(raw, 0), 1023);
    }
    __syncthreads();

    #pragma unroll
    for (int k = 0; k < 2; k++) if (val[k]) atomicAdd(&hist[binv[k]], 1u);
    __syncthreads();

    // exclusive scan of 1024 bins (2 bins/thread)
    uint32_t h0 = hist[2 * tid], h1 = hist[2 * tid + 1];
    uint32_t s2 = h0 + h1;
    uint32_t inc = s2;
    #pragma unroll
    for (int o = 1; o < 32; o <<= 1) {
        uint32_t v = __shfl_up_sync(0xffffffffu, inc, o);
        if ((tid & 31) >= o) inc += v;
    }
    if ((tid & 31) == 31) wsum[tid >> 5] = inc;
    __syncthreads();
    if (tid < 16) {
        uint32_t v = wsum[tid], in2 = v;
        #pragma unroll
        for (int o = 1; o < 16; o <<= 1) {
            uint32_t x = __shfl_up_sync(0x0000ffffu, in2, o);
            if (tid >= o) in2 += x;
        }
        wsum[tid] = in2 - v;   // exclusive warp base
    }
    __syncthreads();
    uint32_t excl = wsum[tid >> 5] + (inc - s2);   // cumexcl at bin 2*tid
    hist[2 * tid]     = excl;
    hist[2 * tid + 1] = excl + h0;
    if (tid == 511) hist[1024] = excl + s2;        // total valid
    if (excl + h0 <= MSEL) atomicMax(&s_bsel, 2 * tid + 1);
    if (excl + s2 <= MSEL) atomicMax(&s_bsel, 2 * tid + 2);
    __syncthreads();

    const int Bsel  = s_bsel;
    const int P     = (int)hist[Bsel];     // exact top-P count, P <= MSEL
    const int total = (int)hist[1024];

    // compact exact top-P candidates
    #pragma unroll
    for (int k = 0; k < 2; k++) {
        int i = tid + k * 512;
        if (val[k] && binv[k] < (uint32_t)Bsel) {
            int pos = atomicAdd(&s_cnt, 1);
            selk[pos] = (((uint64_t)key[k]) << 32) | (uint32_t)i;
        }
    }
    __syncthreads();
    if (tid < MSEL && tid >= P) selk[tid] = ~0ull;
    __syncthreads();

    // bitonic sort 256 (score desc, idx asc)
    for (int k2 = 2; k2 <= MSEL; k2 <<= 1) {
        for (int j = k2 >> 1; j > 0; j >>= 1) {
            if (tid < MSEL) {
                int ixj = tid ^ j;
                if (ixj > tid) {
                    uint64_t a = selk[tid], d2 = selk[ixj];
                    bool up = ((tid & k2) == 0);
                    if ((a > d2) == up) { selk[tid] = d2; selk[ixj] = a; }
                }
            }
            __syncthreads();
        }
    }

    // preload candidate mask rows into smem (sorted rank order)
    for (int l = tid; l < P * 32; l += 512) {
        int r = l >> 5, w2 = l & 31;
        int o = (int)((uint32_t)selk[r] & (NN - 1));
        rows[(r << 5) | w2] = g_mask[(b * NN + o) * 32 + w2];
    }
    __syncthreads();

    // greedy on warp 0: suppressed bitmap lane-distributed
    if (tid < 32) {
        uint32_t sup = 0; int kc = 0;
        for (int p = 0; p < P; p++) {
            uint32_t row = rows[(p << 5) | tid];
            uint64_t kk  = selk[p];
            uint32_t o   = (uint32_t)kk & (NN - 1);
            uint32_t wv  = __shfl_sync(0xffffffffu, sup, (int)(o >> 5));
            if (!((wv >> (o & 31)) & 1u)) {
                if (tid == 0) { kept_i[kc] = (int)o; kept_s[kc] = undbits_pos((uint32_t)(kk >> 32)); }
                sup |= row;
                kc++;
                if (kc == KPC) break;
            }
        }
        if (tid == 0) s_kc = kc;
    }
    __syncthreads();
    int kc = s_kc;

    // fallback: selection exhausted before 100 kept and more valid exist
    if (kc < KPC && P < total) {
        uint64_t* keys = (uint64_t*)rows;   // 8KB of the 32KB rows area
        #pragma unroll
        for (int k = 0; k < 2; k++) {
            int i = tid + k * 512;
            uint32_t kb = val[k] ? key[k] : 0xFFFFFFFFu;
            keys[i] = (((uint64_t)kb) << 32) | (uint32_t)i;
        }
        __syncthreads();
        for (int kk2 = 2; kk2 <= NN; kk2 <<= 1) {
            for (int j = kk2 >> 1; j > 0; j >>= 1) {
                #pragma unroll
                for (int t2 = 0; t2 < 2; t2++) {
                    int i2 = tid + t2 * 512, ixj = i2 ^ j;
                    if (ixj > i2) {
                        uint64_t a = keys[i2], d2 = keys[ixj];
                        bool up = ((i2 & kk2) == 0);
                        if ((a > d2) == up) { keys[i2] = d2; keys[ixj] = a; }
                    }
                }
                __syncthreads();
            }
        }
        if (tid < 32) {
            uint32_t sup = 0; int kc2 = 0;
            for (int p = 0; p < NN; p++) {
                uint64_t kk = keys[p];
                if ((uint32_t)(kk >> 32) == 0xFFFFFFFFu) break;
                uint32_t o   = (uint32_t)kk & (NN - 1);
                uint32_t row = g_mask[(b * NN + o) * 32 + tid];
                uint32_t wv  = __shfl_sync(0xffffffffu, sup, (int)(o >> 5));
                if (!((wv >> (o & 31)) & 1u)) {
                    if (tid == 0) { kept_i[kc2] = (int)o; kept_s[kc2] = undbits_pos((uint32_t)(kk >> 32)); }
                    sup |= row;
                    kc2++;
                    if (kc2 == KPC) break;
                }
            }
            if (tid == 0) s_kc = kc2;
        }
        __syncthreads();
        kc = s_kc;
    }

    if (tid < KPC) {
        int slot = (b * CC + c) * KPC + tid;
        if (tid < kc) { g_stage_s[slot] = kept_s[tid]; g_stage_b[slot] = kept_i[tid]; }
        else          { g_stage_s[slot] = NEGV;        g_stage_b[slot] = 0; }
    }
}

// ---------------- K3: per-image top-300 of 8000 + output ----------------
__global__ void __launch_bounds__(1024) k_final(const float* __restrict__ boxes,
                                                float* __restrict__ out) {
    __shared__ uint32_t hist[4097];
    __shared__ uint64_t skeys[1024];
    __shared__ uint32_t wsum[32];
    __shared__ int      s_cnt, s_bsel, s_total, s_m;

    const int b   = blockIdx.x;
    const int tid = threadIdx.x;
    const int M   = CC * KPC;                    // 8000
    const uint32_t BASE13 = 0x203FF;             // dbits(1.0f) >> 13

    #pragma unroll
    for (int k = 0; k < 4; k++) hist[tid * 4 + k] = 0;
    if (tid == 0) { hist[4096] = 0; s_cnt = 0; s_bsel = 0; }

    float vals[8]; int idxs[8]; uint32_t keyb[8]; uint32_t binb[8]; bool valb[8];
    #pragma unroll
    for (int k = 0; k < 8; k++) {
        int f = tid + k * 1024;
        float s = (f < M) ? g_stage_s[b * M + f] : NEGV;
        vals[k] = s; idxs[k] = (f < M) ? f : 0;
        valb[k] = (s > NEGV * 0.5f);
        keyb[k] = dbits(s);
        int raw = (int)(keyb[k] >> 13) - (int)BASE13;
        binb[k] = (uint32_t)min(max(raw, 0), 4095);
    }
    __syncthreads();
    #pragma unroll
    for (int k = 0; k < 8; k++) if (valb[k]) atomicAdd(&hist[binb[k]], 1u);
    __syncthreads();

    // exclusive scan of 4096 bins (4/thread)
    uint32_t h[4];
    #pragma unroll
    for (int k = 0; k < 4; k++) h[k] = hist[4 * tid + k];
    uint32_t s4 = h[0] + h[1] + h[2] + h[3];
    uint32_t inc = s4;
    #pragma unroll
    for (int o = 1; o < 32; o <<= 1) {
        uint32_t v = __shfl_up_sync(0xffffffffu, inc, o);
        if ((tid & 31) >= o) inc += v;
    }
    if ((tid & 31) == 31) wsum[tid >> 5] = inc;
    __syncthreads();
    if (tid < 32) {
        uint32_t v = wsum[tid], in2 = v;
        #pragma unroll
        for (int o = 1; o < 32; o <<= 1) {
            uint32_t x = __shfl_up_sync(0xffffffffu, in2, o);
            if (tid >= o) in2 += x;
        }
        wsum[tid] = in2 - v;
    }
    __syncthreads();
    uint32_t excl = wsum[tid >> 5] + (inc - s4);
    uint32_t cum0 = excl, cum1 = excl + h[0], cum2 = cum1 + h[1], cum3 = cum2 + h[2], cum4 = excl + s4;
    hist[4 * tid] = cum0; hist[4 * tid + 1] = cum1; hist[4 * tid + 2] = cum2; hist[4 * tid + 3] = cum3;
    if (tid == 1023) hist[4096] = cum4;
    if (cum1 <= 1024u) atomicMax(&s_bsel, 4 * tid + 1);
    if (cum2 <= 1024u) atomicMax(&s_bsel, 4 * tid + 2);
    if (cum3 <= 1024u) atomicMax(&s_bsel, 4 * tid + 3);
    if (cum4 <= 1024u) atomicMax(&s_bsel, 4 * tid + 4);
    __syncthreads();

    const int Bsel  = s_bsel;
    int P           = (int)hist[Bsel];
    const int total = (int)hist[4096];

    if (P >= MAXT || P >= total) {
        // exact top-P select path
        #pragma unroll
        for (int k = 0; k < 8; k++) {
            if (valb[k] && binb[k] < (uint32_t)Bsel) {
                int pos = atomicAdd(&s_cnt, 1);
                if (pos < 1024) skeys[pos] = (((uint64_t)keyb[k]) << 32) | (uint32_t)idxs[k];
            }
        }
        if (tid == 0) s_m = P;
    } else {
        // fallback: bisection on pivot (correct for any distribution)
        float lo = 0.0f, hi = 1.0f;
        for (int it = 0; it < 30; it++) {
            float mid = 0.5f * (lo + hi);
            int cnt = 0;
            #pragma unroll
            for (int k = 0; k < 8; k++) cnt += (vals[k] > mid);
            #pragma unroll
            for (int o = 16; o; o >>= 1) cnt += __shfl_down_sync(0xffffffffu, cnt, o);
            if ((tid & 31) == 0) wsum[tid >> 5] = (uint32_t)cnt;
            __syncthreads();
            if (tid == 0) {
                int tot = 0;
                #pragma unroll
                for (int w2 = 0; w2 < 32; w2++) tot += (int)wsum[w2];
                s_total = tot;
            }
            __syncthreads();
            if (s_total >= MAXT) lo = mid; else hi = mid;
            __syncthreads();
        }
        if (tid == 0) s_cnt = 0;
        __syncthreads();
        #pragma unroll
        for (int k = 0; k < 8; k++) {
            if (vals[k] > lo) {
                int pos = atomicAdd(&s_cnt, 1);
                if (pos < 1024) skeys[pos] = (((uint64_t)dbits(vals[k])) << 32) | (uint32_t)idxs[k];
            }
        }
        __syncthreads();
        if (tid == 0) s_m = min(s_cnt, 1024);
    }
    __syncthreads();
    const int m = s_m;
    if (tid >= m) skeys[tid] = 0xFFFFFFFFFFFFFFFFull;
    __syncthreads();

    // bitonic sort 1024 u64
    for (int k2 = 2; k2 <= 1024; k2 <<= 1) {
        for (int j = k2 >> 1; j > 0; j >>= 1) {
            int ixj = tid ^ j;
            if (ixj > tid) {
                uint64_t a = skeys[tid], d2 = skeys[ixj];
                bool up = ((tid & k2) == 0);
                if ((a > d2) == up) { skeys[tid] = d2; skeys[ixj] = a; }
            }
            __syncthreads();
        }
    }

    if (tid < MAXT) {
        bool valid = (tid < m);
        float sc = 0.0f, cls = 0.0f, bx0 = 0.0f, bx1 = 0.0f, bx2 = 0.0f, bx3 = 0.0f;
        if (valid) {
            uint64_t kk = skeys[tid];
            int f = (int)((uint32_t)kk);
            sc  = g_stage_s[b * M + f];
            cls = (float)(f / KPC);
            int bidx = g_stage_b[b * M + f];
            float4 bv = reinterpret_cast<const float4*>(boxes)[b * NN + bidx];
            bx0 = fminf(fmaxf(bv.x, 0.0f), 1.0f);
            bx1 = fminf(fmaxf(bv.y, 0.0f), 1.0f);
            bx2 = fminf(fmaxf(bv.z, 0.0f), 1.0f);
            bx3 = fminf(fmaxf(bv.w, 0.0f), 1.0f);
        }
        out[b * MAXT + tid] = sc;
        float* ob = out + BB * MAXT + (b * MAXT + tid) * 4;
        ob[0] = bx0; ob[1] = bx1; ob[2] = bx2; ob[3] = bx3;
        out[BB * MAXT * 5 + b * MAXT + tid] = cls;
    }
    if (tid == 0) out[BB * MAXT * 6 + b] = (float)min(m, MAXT);
}

// ---------------- launch ----------------
extern "C" void kernel_launch(void* const* d_in, const int* in_sizes, int n_in,
                              void* d_out, int out_size) {
    const float* scores = (const float*)d_in[0];   // [4,1024,80] f32
    const float* boxes  = (const float*)d_in[1];   // [4,1024,1,4] f32
    float* out = (float*)d_out;

    k_mask<<<dim3(128, BB), 256>>>((const float4*)boxes);
    k_nms<<<dim3(CC, BB), 512>>>(scores);
    k_final<<<BB, 1024>>>(boxes, out);
}